// round 15
// baseline (speedup 1.0000x reference)
#include <cuda_runtime.h>
#include <math.h>
#include <stdint.h>

// Problem constants
#define S_TOK 65536
#define H_DIM 768
#define T_TYP 6
#define K_TOP 3
#define WIN   15

// ---------------------------------------------------------------------------
// Device scratch
// ---------------------------------------------------------------------------
__device__ float g_start[T_TYP * S_TOK];   // column-major [t][s]
__device__ float g_end  [T_TYP * S_TOK];   // column-major [t][s]
__device__ float g_pooled[H_DIM];          // atomic-accumulated column sums of X
__device__ float g_s[T_TYP];               // per-column sum exp(x) (unshifted)
__device__ float g_topv[T_TYP * K_TOP];    // top-3 raw start scores (desc)
__device__ int   g_topi[T_TYP * K_TOP];    // their indices

// ---------------------------------------------------------------------------
// Kernel 0: zero the pooled accumulator (required every graph replay)
// ---------------------------------------------------------------------------
__global__ void zero_pool_kernel() {
    int i = blockIdx.x * blockDim.x + threadIdx.x;
    if (i < H_DIM) g_pooled[i] = 0.0f;
}

// ---------------------------------------------------------------------------
// Helpers
// ---------------------------------------------------------------------------
__device__ __forceinline__ float wsum1(float v) {
#pragma unroll
    for (int off = 16; off > 0; off >>= 1)
        v += __shfl_xor_sync(0xffffffffu, v, off);
    return v;
}

__device__ __forceinline__ float comp4(float4 v, int kk) {
    return kk == 0 ? v.x : (kk == 1 ? v.y : (kk == 2 ? v.z : v.w));
}

// ---------------------------------------------------------------------------
// Kernel 1: fused GEMV x12 + column-sum of X.
// 1024 blocks x 256 threads. Warp owns 8 contiguous rows (2 groups of 4).
// Lanes split H: lane covers h = i*128 + lane*4 .. +3 for chunk i in 0..5.
//
// W smem layout: 192 disjoint regions, one per (chunk i, lane L), each
// holding the 48 weights {w[k][c] : k = i*128+4L+kk, kk<4, c<12} at
// region*49 + kk*12 + c. The 49-word pad makes the lane stride 49 ->
// bank = (17*L + const) mod 32, gcd(17,32)=1 -> conflict-free scalar LDS.
// (Previous [k][12] layout had a 16-way conflict: 48*L mod 32 hits 2 banks.)
// ---------------------------------------------------------------------------
#define REG_STRIDE 49
__global__ void __launch_bounds__(256, 2)
main_pass_kernel(const float* __restrict__ X,
                 const float* __restrict__ Ws,
                 const float* __restrict__ We) {
    __shared__ float swc[192 * REG_STRIDE];   // 37,632 B
    __shared__ __align__(16) float sp[H_DIM]; // 3,072 B

    const int tid    = threadIdx.x;
    const int warpId = tid >> 5;
    const int lane   = tid & 31;

    // ---- stage weights into padded per-(i,lane) regions (cheap index math) --
    {
        // each warp fills 24 regions; lane handles within-region slots lane, lane+32
        const int w_in0 = lane;          // < 32 always valid (48 slots)
        const int kk0 = w_in0 / 12, c0 = w_in0 % 12;
        const int w_in1 = lane + 32;     // valid if < 48  (lanes 0..15)
        const int kk1 = w_in1 / 12, c1 = w_in1 % 12;
        for (int rr = 0; rr < 24; rr++) {
            const int region = warpId * 24 + rr;
            const int i = region >> 5;
            const int L = region & 31;
            const int kbase = i * 128 + L * 4;
            {
                const int k = kbase + kk0;
                swc[region * REG_STRIDE + w_in0] =
                    (c0 < 6) ? Ws[k * 6 + c0] : We[k * 6 + (c0 - 6)];
            }
            if (w_in1 < 48) {
                const int k = kbase + kk1;
                swc[region * REG_STRIDE + w_in1] =
                    (c1 < 6) ? Ws[k * 6 + c1] : We[k * 6 + (c1 - 6)];
            }
        }
    }
    __syncthreads();

    const int wg = blockIdx.x * 8 + warpId;   // 8192 warps total

    float4 pacc[6];
#pragma unroll
    for (int i = 0; i < 6; i++) pacc[i] = make_float4(0.f, 0.f, 0.f, 0.f);

#pragma unroll
    for (int grp = 0; grp < 2; grp++) {
        const int row0 = wg * 8 + grp * 4;
        const float* xp = X + (size_t)row0 * H_DIM + lane * 4;

        float a[4][12];
#pragma unroll
        for (int r = 0; r < 4; r++)
#pragma unroll
            for (int c = 0; c < 12; c++) a[r][c] = 0.0f;

#pragma unroll
        for (int i = 0; i < 6; i++) {
            float4 x0 = *(const float4*)(xp + 0 * H_DIM + i * 128);
            float4 x1 = *(const float4*)(xp + 1 * H_DIM + i * 128);
            float4 x2 = *(const float4*)(xp + 2 * H_DIM + i * 128);
            float4 x3 = *(const float4*)(xp + 3 * H_DIM + i * 128);

            pacc[i].x += (x0.x + x1.x) + (x2.x + x3.x);
            pacc[i].y += (x0.y + x1.y) + (x2.y + x3.y);
            pacc[i].z += (x0.z + x1.z) + (x2.z + x3.z);
            pacc[i].w += (x0.w + x1.w) + (x2.w + x3.w);

            const float* wb = swc + (i * 32 + lane) * REG_STRIDE;
#pragma unroll
            for (int kk = 0; kk < 4; kk++) {
                float w[12];
#pragma unroll
                for (int c = 0; c < 12; c++) w[c] = wb[kk * 12 + c];
                const float xv0 = comp4(x0, kk);
                const float xv1 = comp4(x1, kk);
                const float xv2 = comp4(x2, kk);
                const float xv3 = comp4(x3, kk);
#pragma unroll
                for (int c = 0; c < 12; c++) {
                    a[0][c] = fmaf(w[c], xv0, a[0][c]);
                    a[1][c] = fmaf(w[c], xv1, a[1][c]);
                    a[2][c] = fmaf(w[c], xv2, a[2][c]);
                    a[3][c] = fmaf(w[c], xv3, a[3][c]);
                }
            }
        }

        // reduce 12 scores per row across the warp, lane 0 stores
#pragma unroll
        for (int r = 0; r < 4; r++) {
            float s[12];
#pragma unroll
            for (int c = 0; c < 12; c++) s[c] = wsum1(a[r][c]);
            if (lane == 0) {
                const int row = row0 + r;
#pragma unroll
                for (int c = 0; c < 6; c++)
                    g_start[c * S_TOK + row] = s[c];
#pragma unroll
                for (int c = 0; c < 6; c++)
                    g_end[c * S_TOK + row] = s[6 + c];
            }
        }
    }

    // combine pooled partials across the 8 warps (serialized, no smem atomics)
    for (int w = 0; w < 8; w++) {
        if (warpId == w) {
#pragma unroll
            for (int i = 0; i < 6; i++) {
                float4* p = (float4*)&sp[i * 128 + lane * 4];
                if (w == 0) {
                    *p = pacc[i];
                } else {
                    float4 cur = *p;
                    cur.x += pacc[i].x; cur.y += pacc[i].y;
                    cur.z += pacc[i].z; cur.w += pacc[i].w;
                    *p = cur;
                }
            }
        }
        __syncthreads();
    }
    for (int h = tid; h < H_DIM; h += 256) atomicAdd(&g_pooled[h], sp[h]);
}

// ---------------------------------------------------------------------------
// Kernel 2: per-column sumexp (unshifted; scores are O(1) so no overflow,
// and softmax values are shift-invariant) + top-3 of raw start scores.
// 6 blocks x 1024 threads, float4 coalesced scan + smem tree merge.
// ---------------------------------------------------------------------------
__device__ __forceinline__ bool better(float av, int ai, float bv, int bi) {
    return (av > bv) || (av == bv && ai < bi);
}
__device__ __forceinline__ void insert3(float cv, int ci,
                                        float& v0, int& i0,
                                        float& v1, int& i1,
                                        float& v2, int& i2) {
    if (better(cv, ci, v0, i0)) {
        v2 = v1; i2 = i1; v1 = v0; i1 = i0; v0 = cv; i0 = ci;
    } else if (better(cv, ci, v1, i1)) {
        v2 = v1; i2 = i1; v1 = cv; i1 = ci;
    } else if (better(cv, ci, v2, i2)) {
        v2 = cv; i2 = ci;
    }
}

__global__ void __launch_bounds__(1024) stats_kernel() {
    __shared__ float sms[1024];
    __shared__ float smv[1024 * 3];
    __shared__ int   smi[1024 * 3];

    const int t   = blockIdx.x;
    const int tid = threadIdx.x;
    const float4* __restrict__ col4 =
        (const float4*)(g_start + (size_t)t * S_TOK);

    float s = 0.0f;
    float v0 = -INFINITY, v1 = -INFINITY, v2 = -INFINITY;
    int   i0 = 0x7fffffff, i1 = 0x7fffffff, i2 = 0x7fffffff;

    for (int jj = tid; jj < S_TOK / 4; jj += 1024) {
        float4 v = col4[jj];
        s += (__expf(v.x) + __expf(v.y)) + (__expf(v.z) + __expf(v.w));
        const int jb = jj * 4;
        insert3(v.x, jb + 0, v0, i0, v1, i1, v2, i2);
        insert3(v.y, jb + 1, v0, i0, v1, i1, v2, i2);
        insert3(v.z, jb + 2, v0, i0, v1, i1, v2, i2);
        insert3(v.w, jb + 3, v0, i0, v1, i1, v2, i2);
    }

    sms[tid] = s;
    smv[tid * 3 + 0] = v0; smi[tid * 3 + 0] = i0;
    smv[tid * 3 + 1] = v1; smi[tid * 3 + 1] = i1;
    smv[tid * 3 + 2] = v2; smi[tid * 3 + 2] = i2;
    __syncthreads();

    for (int stride = 512; stride >= 1; stride >>= 1) {
        if (tid < stride) {
            int o = tid + stride;
            s += sms[o];
#pragma unroll
            for (int q = 0; q < 3; q++)
                insert3(smv[o * 3 + q], smi[o * 3 + q], v0, i0, v1, i1, v2, i2);
            sms[tid] = s;
            smv[tid * 3 + 0] = v0; smi[tid * 3 + 0] = i0;
            smv[tid * 3 + 1] = v1; smi[tid * 3 + 1] = i1;
            smv[tid * 3 + 2] = v2; smi[tid * 3 + 2] = i2;
        }
        __syncthreads();
    }

    if (tid == 0) {
        g_s[t] = s;
        g_topv[t * 3 + 0] = v0; g_topi[t * 3 + 0] = i0;
        g_topv[t * 3 + 1] = v1; g_topi[t * 3 + 1] = i1;
        g_topv[t * 3 + 2] = v2; g_topi[t * 3 + 2] = i2;
    }
}

// ---------------------------------------------------------------------------
// Kernel 3: pooled-mean MLP (exact GELU + sigmoid) + window argmax + outputs.
// 1024 threads: 16-way K-split of the 768x64 GEMV (48 global loads/thread,
// latency-overlapped) instead of the former 4-way split that made this
// kernel 20 us. Output: [conf(18) | starts(18) | ends(18) | valid(18)] f32.
// ---------------------------------------------------------------------------
__global__ void __launch_bounds__(1024)
final_kernel(const float* __restrict__ W1, const float* __restrict__ b1,
             const float* __restrict__ W2, const float* __restrict__ b2,
             float* __restrict__ out) {
    __shared__ float sp[H_DIM];
    __shared__ float spart[16][64];
    __shared__ float sh[64];
    __shared__ float stc[T_TYP];

    const int tid = threadIdx.x;

    if (tid < H_DIM) sp[tid] = g_pooled[tid] * (1.0f / (float)S_TOK);
    __syncthreads();

    {   // h = gelu(pooled @ W1 + b1), split K over 16 partitions of 48
        const int j = tid & 63, part = tid >> 6;
        const int k0 = part * 48;
        float acc = 0.0f;
#pragma unroll 4
        for (int k = k0; k < k0 + 48; k++)
            acc = fmaf(sp[k], W1[k * 64 + j], acc);
        spart[part][j] = acc;
    }
    __syncthreads();

    if (tid < 64) {
        float z = b1[tid];
#pragma unroll
        for (int p = 0; p < 16; p++) z += spart[p][tid];
        sh[tid] = 0.5f * z * (1.0f + erff(z * 0.70710678118654752f));
    }
    __syncthreads();

    if (tid < T_TYP) {
        float z = b2[tid];
#pragma unroll 8
        for (int j = 0; j < 64; j++)
            z = fmaf(sh[j], W2[j * 6 + tid], z);
        stc[tid] = 1.0f / (1.0f + expf(-z));
    }
    __syncthreads();

    if (tid < T_TYP * K_TOP) {
        const int t = tid / K_TOP;
        const int idx = g_topi[tid];
        const float v = g_topv[tid];
        const float prob = __expf(v) / g_s[t];   // softmax top value (unshifted)

        const float* __restrict__ ecol = g_end + (size_t)t * S_TOK;
        float best = -INFINITY;
        int   boff = 0;
#pragma unroll
        for (int j = 0; j < WIN; j++) {
            int p = idx + j;
            if (p < S_TOK) {
                float ev = ecol[p];
                if (ev > best) { best = ev; boff = j; }
            }
        }

        const float tc = stc[t];
        const bool valid = (tc >= 0.3f) && (prob >= 0.15f);
        out[tid]          = valid ? prob * tc : 0.0f;
        out[18 + tid]     = (float)idx;
        out[36 + tid]     = (float)(idx + boff + 1);
        out[54 + tid]     = valid ? 1.0f : 0.0f;
    }
}

// ---------------------------------------------------------------------------
// Launch. Inputs (metadata order):
// 0 token_embeds (S*H f32), 1 W_start (H*T), 2 b_start, 3 W_end (H*T),
// 4 b_end, 5 W1 (H*64), 6 b1 (64), 7 W2 (64*T), 8 b2 (T)
// b_start/b_end are irrelevant to the outputs (softmax & windowed-argmax are
// invariant to per-column shifts; the reference biases are zeros anyway).
// ---------------------------------------------------------------------------
extern "C" void kernel_launch(void* const* d_in, const int* in_sizes, int n_in,
                              void* d_out, int out_size) {
    const float* X  = (const float*)d_in[0];
    const float* Ws = (const float*)d_in[1];
    const float* We = (const float*)d_in[3];
    const float* W1 = (const float*)d_in[5];
    const float* b1 = (const float*)d_in[6];
    const float* W2 = (const float*)d_in[7];
    const float* b2 = (const float*)d_in[8];
    float* out = (float*)d_out;

    zero_pool_kernel<<<3, 256>>>();
    main_pass_kernel<<<1024, 256>>>(X, Ws, We);
    stats_kernel<<<T_TYP, 1024>>>();
    final_kernel<<<1, 1024>>>(W1, b1, W2, b2, out);
}

// round 16
// speedup vs baseline: 1.5037x; 1.5037x over previous
#include <cuda_runtime.h>
#include <math.h>
#include <stdint.h>

// Problem constants
#define S_TOK 65536
#define H_DIM 768
#define T_TYP 6
#define K_TOP 3
#define WIN   15

// ---------------------------------------------------------------------------
// Device scratch (device globals are zero-initialized at module load)
// ---------------------------------------------------------------------------
__device__ float g_start[T_TYP * S_TOK];   // column-major [t][s]
__device__ float g_end  [T_TYP * S_TOK];   // column-major [t][s]
__device__ float g_pooled[H_DIM];          // accumulated column sums of X
                                           // (final_kernel resets to 0 -> replay-safe)
__device__ float g_s[T_TYP];               // per-column sum exp(x) (unshifted)
__device__ float g_topv[T_TYP * K_TOP];    // top-3 raw start scores (desc)
__device__ int   g_topi[T_TYP * K_TOP];    // their indices

// ---------------------------------------------------------------------------
// Helpers (functions, not macros — see R13 macro-hygiene bug)
// ---------------------------------------------------------------------------
__device__ __forceinline__ float4 wsum4(float4 v) {
#pragma unroll
    for (int off = 16; off > 0; off >>= 1) {
        v.x += __shfl_xor_sync(0xffffffffu, v.x, off);
        v.y += __shfl_xor_sync(0xffffffffu, v.y, off);
        v.z += __shfl_xor_sync(0xffffffffu, v.z, off);
        v.w += __shfl_xor_sync(0xffffffffu, v.w, off);
    }
    return v;
}

__device__ __forceinline__ void fma4(float4& acc, const float4 wv, const float xs) {
    acc.x = fmaf(wv.x, xs, acc.x);
    acc.y = fmaf(wv.y, xs, acc.y);
    acc.z = fmaf(wv.z, xs, acc.z);
    acc.w = fmaf(wv.w, xs, acc.w);
}

// ---------------------------------------------------------------------------
// Kernel 1: fused GEMV x12 + column-sum of X.
// 1024 blocks x 256 threads. Warp owns 8 contiguous rows, 4 groups of 2.
// Lanes split H: lane L covers k = i*128 + 4L .. +3 for chunk i in 0..5.
//
// EVERYTHING register-resident is a NAMED variable (macro-expanded bodies):
// no float arrays indexed by loop vars -> nothing ptxas can demote to local
// memory (prime suspect for the 8x slowdown of R14/R15).
//
// W smem: region per (chunk i, lane L), 68-float stride (region base 272 B ->
// 16B-aligned; 68 = 4 mod 32 -> within each 8-lane LDS.128 phase, banks
// 4L+const are distinct -> conflict-free). Region content: kk*16 + c holds
// w[k = i*128+4L+kk][c], c<12 (slots 12..15 padding, never read).
// ---------------------------------------------------------------------------
#define REG_STRIDE 68

#define DO_KK(kk, XC0, XC1)                                       \
    {                                                             \
        float4 wv0 = *(const float4*)(wb + (kk) * 16 + 0);        \
        float4 wv1 = *(const float4*)(wb + (kk) * 16 + 4);        \
        float4 wv2 = *(const float4*)(wb + (kk) * 16 + 8);        \
        fma4(A0, wv0, XC0); fma4(A1, wv1, XC0); fma4(A2, wv2, XC0);\
        fma4(B0, wv0, XC1); fma4(B1, wv1, XC1); fma4(B2, wv2, XC1);\
    }

#define DO_CHUNK(ii, PA)                                                    \
    {                                                                       \
        float4 x0 = *(const float4*)(xp0 + (ii) * 128);                     \
        float4 x1 = *(const float4*)(xp1 + (ii) * 128);                     \
        PA.x += x0.x + x1.x;                                                \
        PA.y += x0.y + x1.y;                                                \
        PA.z += x0.z + x1.z;                                                \
        PA.w += x0.w + x1.w;                                                \
        const float* wb = swc + ((ii) * 32 + lane) * REG_STRIDE;            \
        DO_KK(0, x0.x, x1.x)                                                \
        DO_KK(1, x0.y, x1.y)                                                \
        DO_KK(2, x0.z, x1.z)                                                \
        DO_KK(3, x0.w, x1.w)                                                \
    }

__global__ void __launch_bounds__(256, 2)
main_pass_kernel(const float* __restrict__ X,
                 const float* __restrict__ Ws,
                 const float* __restrict__ We) {
    __shared__ __align__(16) float swc[192 * REG_STRIDE];   // 52,224 B
    __shared__ __align__(16) float sp[H_DIM];               //  3,072 B

    const int tid    = threadIdx.x;
    const int warpId = tid >> 5;
    const int lane   = tid & 31;

    // ---- stage weights: 192 regions x 48 useful floats ----------------------
    for (int idx = tid; idx < 192 * 48; idx += 256) {
        const int region = idx / 48;
        const int within = idx - region * 48;
        const int kk = within / 12;
        const int c  = within - kk * 12;
        const int i  = region >> 5;
        const int L  = region & 31;
        const int k  = i * 128 + L * 4 + kk;
        swc[region * REG_STRIDE + kk * 16 + c] =
            (c < 6) ? Ws[k * 6 + c] : We[k * 6 + (c - 6)];
    }
    __syncthreads();

    const int wg = blockIdx.x * 8 + warpId;   // 8192 warps total

    float4 pa0 = make_float4(0.f, 0.f, 0.f, 0.f);
    float4 pa1 = make_float4(0.f, 0.f, 0.f, 0.f);
    float4 pa2 = make_float4(0.f, 0.f, 0.f, 0.f);
    float4 pa3 = make_float4(0.f, 0.f, 0.f, 0.f);
    float4 pa4 = make_float4(0.f, 0.f, 0.f, 0.f);
    float4 pa5 = make_float4(0.f, 0.f, 0.f, 0.f);

    for (int g = 0; g < 4; g++) {            // 4 groups of 2 rows
        const int row0 = wg * 8 + g * 2;
        const float* xp0 = X + (size_t)row0 * H_DIM + lane * 4;
        const float* xp1 = xp0 + H_DIM;

        float4 A0 = make_float4(0.f, 0.f, 0.f, 0.f);
        float4 A1 = make_float4(0.f, 0.f, 0.f, 0.f);
        float4 A2 = make_float4(0.f, 0.f, 0.f, 0.f);
        float4 B0 = make_float4(0.f, 0.f, 0.f, 0.f);
        float4 B1 = make_float4(0.f, 0.f, 0.f, 0.f);
        float4 B2 = make_float4(0.f, 0.f, 0.f, 0.f);

        DO_CHUNK(0, pa0)
        DO_CHUNK(1, pa1)
        DO_CHUNK(2, pa2)
        DO_CHUNK(3, pa3)
        DO_CHUNK(4, pa4)
        DO_CHUNK(5, pa5)

        A0 = wsum4(A0); A1 = wsum4(A1); A2 = wsum4(A2);
        B0 = wsum4(B0); B1 = wsum4(B1); B2 = wsum4(B2);

        if (lane == 0) {
            const int r0 = row0, r1 = row0 + 1;
            g_start[0 * S_TOK + r0] = A0.x;
            g_start[1 * S_TOK + r0] = A0.y;
            g_start[2 * S_TOK + r0] = A0.z;
            g_start[3 * S_TOK + r0] = A0.w;
            g_start[4 * S_TOK + r0] = A1.x;
            g_start[5 * S_TOK + r0] = A1.y;
            g_end  [0 * S_TOK + r0] = A1.z;
            g_end  [1 * S_TOK + r0] = A1.w;
            g_end  [2 * S_TOK + r0] = A2.x;
            g_end  [3 * S_TOK + r0] = A2.y;
            g_end  [4 * S_TOK + r0] = A2.z;
            g_end  [5 * S_TOK + r0] = A2.w;

            g_start[0 * S_TOK + r1] = B0.x;
            g_start[1 * S_TOK + r1] = B0.y;
            g_start[2 * S_TOK + r1] = B0.z;
            g_start[3 * S_TOK + r1] = B0.w;
            g_start[4 * S_TOK + r1] = B1.x;
            g_start[5 * S_TOK + r1] = B1.y;
            g_end  [0 * S_TOK + r1] = B1.z;
            g_end  [1 * S_TOK + r1] = B1.w;
            g_end  [2 * S_TOK + r1] = B2.x;
            g_end  [3 * S_TOK + r1] = B2.y;
            g_end  [4 * S_TOK + r1] = B2.z;
            g_end  [5 * S_TOK + r1] = B2.w;
        }
    }

    // ---- combine pooled partials across the 8 warps (named, no arrays) ------
#define COMB(IDX, PA)                                              \
    {                                                              \
        float4* p = (float4*)&sp[(IDX) * 128 + lane * 4];          \
        if (w == 0) {                                              \
            *p = PA;                                               \
        } else {                                                   \
            float4 t = *p;                                         \
            t.x += PA.x; t.y += PA.y; t.z += PA.z; t.w += PA.w;    \
            *p = t;                                                \
        }                                                          \
    }
    for (int w = 0; w < 8; w++) {
        if (warpId == w) {
            COMB(0, pa0) COMB(1, pa1) COMB(2, pa2)
            COMB(3, pa3) COMB(4, pa4) COMB(5, pa5)
        }
        __syncthreads();
    }
#undef COMB
    for (int h = tid; h < H_DIM; h += 256) atomicAdd(&g_pooled[h], sp[h]);
}

// ---------------------------------------------------------------------------
// Kernel 2: per-column sumexp (unshifted; scores are O(1), softmax values are
// shift-invariant) + top-3 of raw start scores. 6 blocks x 1024 threads.
// ---------------------------------------------------------------------------
__device__ __forceinline__ bool better(float av, int ai, float bv, int bi) {
    return (av > bv) || (av == bv && ai < bi);
}
__device__ __forceinline__ void insert3(float cv, int ci,
                                        float& v0, int& i0,
                                        float& v1, int& i1,
                                        float& v2, int& i2) {
    if (better(cv, ci, v0, i0)) {
        v2 = v1; i2 = i1; v1 = v0; i1 = i0; v0 = cv; i0 = ci;
    } else if (better(cv, ci, v1, i1)) {
        v2 = v1; i2 = i1; v1 = cv; i1 = ci;
    } else if (better(cv, ci, v2, i2)) {
        v2 = cv; i2 = ci;
    }
}

__global__ void __launch_bounds__(1024) stats_kernel() {
    __shared__ float sms[1024];
    __shared__ float smv[1024 * 3];
    __shared__ int   smi[1024 * 3];

    const int t   = blockIdx.x;
    const int tid = threadIdx.x;
    const float4* __restrict__ col4 =
        (const float4*)(g_start + (size_t)t * S_TOK);

    float s = 0.0f;
    float v0 = -INFINITY, v1 = -INFINITY, v2 = -INFINITY;
    int   i0 = 0x7fffffff, i1 = 0x7fffffff, i2 = 0x7fffffff;

    for (int jj = tid; jj < S_TOK / 4; jj += 1024) {
        float4 v = col4[jj];
        s += (__expf(v.x) + __expf(v.y)) + (__expf(v.z) + __expf(v.w));
        const int jb = jj * 4;
        insert3(v.x, jb + 0, v0, i0, v1, i1, v2, i2);
        insert3(v.y, jb + 1, v0, i0, v1, i1, v2, i2);
        insert3(v.z, jb + 2, v0, i0, v1, i1, v2, i2);
        insert3(v.w, jb + 3, v0, i0, v1, i1, v2, i2);
    }

    sms[tid] = s;
    smv[tid * 3 + 0] = v0; smi[tid * 3 + 0] = i0;
    smv[tid * 3 + 1] = v1; smi[tid * 3 + 1] = i1;
    smv[tid * 3 + 2] = v2; smi[tid * 3 + 2] = i2;
    __syncthreads();

    for (int stride = 512; stride >= 1; stride >>= 1) {
        if (tid < stride) {
            int o = tid + stride;
            s += sms[o];
#pragma unroll
            for (int q = 0; q < 3; q++)
                insert3(smv[o * 3 + q], smi[o * 3 + q], v0, i0, v1, i1, v2, i2);
            sms[tid] = s;
            smv[tid * 3 + 0] = v0; smi[tid * 3 + 0] = i0;
            smv[tid * 3 + 1] = v1; smi[tid * 3 + 1] = i1;
            smv[tid * 3 + 2] = v2; smi[tid * 3 + 2] = i2;
        }
        __syncthreads();
    }

    if (tid == 0) {
        g_s[t] = s;
        g_topv[t * 3 + 0] = v0; g_topi[t * 3 + 0] = i0;
        g_topv[t * 3 + 1] = v1; g_topi[t * 3 + 1] = i1;
        g_topv[t * 3 + 2] = v2; g_topi[t * 3 + 2] = i2;
    }
}

// ---------------------------------------------------------------------------
// Kernel 3: pooled-mean MLP (exact GELU + sigmoid) + window argmax + outputs.
// Also RESETS g_pooled to zero (keeps graph replays deterministic with no
// separate zeroing launch). Output: [conf(18)|starts(18)|ends(18)|valid(18)].
// ---------------------------------------------------------------------------
__global__ void __launch_bounds__(1024)
final_kernel(const float* __restrict__ W1, const float* __restrict__ b1,
             const float* __restrict__ W2, const float* __restrict__ b2,
             float* __restrict__ out) {
    __shared__ float sp[H_DIM];
    __shared__ float spart[16][64];
    __shared__ float sh[64];
    __shared__ float stc[T_TYP];

    const int tid = threadIdx.x;

    if (tid < H_DIM) {
        sp[tid] = g_pooled[tid] * (1.0f / (float)S_TOK);
        g_pooled[tid] = 0.0f;   // reset for next replay
    }
    __syncthreads();

    {   // h = gelu(pooled @ W1 + b1): 16-way K-split, 2 independent accs
        const int j = tid & 63, part = tid >> 6;
        const int k0 = part * 48;
        float acc0 = 0.0f, acc1 = 0.0f;
#pragma unroll 8
        for (int k = 0; k < 48; k += 2) {
            acc0 = fmaf(sp[k0 + k],     W1[(k0 + k) * 64 + j],     acc0);
            acc1 = fmaf(sp[k0 + k + 1], W1[(k0 + k + 1) * 64 + j], acc1);
        }
        spart[part][j] = acc0 + acc1;
    }
    __syncthreads();

    if (tid < 64) {
        float z = b1[tid];
#pragma unroll
        for (int p = 0; p < 16; p++) z += spart[p][tid];
        sh[tid] = 0.5f * z * (1.0f + erff(z * 0.70710678118654752f));
    }
    __syncthreads();

    if (tid < T_TYP) {
        float z = b2[tid];
#pragma unroll 8
        for (int j = 0; j < 64; j++)
            z = fmaf(sh[j], W2[j * 6 + tid], z);
        stc[tid] = 1.0f / (1.0f + expf(-z));
    }
    __syncthreads();

    if (tid < T_TYP * K_TOP) {
        const int t = tid / K_TOP;
        const int idx = g_topi[tid];
        const float v = g_topv[tid];
        const float prob = __expf(v) / g_s[t];   // softmax top value (unshifted)

        const float* __restrict__ ecol = g_end + (size_t)t * S_TOK;
        float best = -INFINITY;
        int   boff = 0;
#pragma unroll
        for (int j = 0; j < WIN; j++) {
            int p = idx + j;
            if (p < S_TOK) {
                float ev = ecol[p];
                if (ev > best) { best = ev; boff = j; }
            }
        }

        const float tc = stc[t];
        const bool valid = (tc >= 0.3f) && (prob >= 0.15f);
        out[tid]          = valid ? prob * tc : 0.0f;
        out[18 + tid]     = (float)idx;
        out[36 + tid]     = (float)(idx + boff + 1);
        out[54 + tid]     = valid ? 1.0f : 0.0f;
    }
}

// ---------------------------------------------------------------------------
// Launch. Inputs (metadata order):
// 0 token_embeds (S*H f32), 1 W_start (H*T), 2 b_start, 3 W_end (H*T),
// 4 b_end, 5 W1 (H*64), 6 b1 (64), 7 W2 (64*T), 8 b2 (T)
// b_start/b_end cannot affect the outputs (softmax & windowed-argmax are
// invariant to per-column shifts; reference biases are zeros anyway).
// ---------------------------------------------------------------------------
extern "C" void kernel_launch(void* const* d_in, const int* in_sizes, int n_in,
                              void* d_out, int out_size) {
    const float* X  = (const float*)d_in[0];
    const float* Ws = (const float*)d_in[1];
    const float* We = (const float*)d_in[3];
    const float* W1 = (const float*)d_in[5];
    const float* b1 = (const float*)d_in[6];
    const float* W2 = (const float*)d_in[7];
    const float* b2 = (const float*)d_in[8];
    float* out = (float*)d_out;

    main_pass_kernel<<<1024, 256>>>(X, Ws, We);
    stats_kernel<<<T_TYP, 1024>>>();
    final_kernel<<<1, 1024>>>(W1, b1, W2, b2, out);
}